// round 6
// baseline (speedup 1.0000x reference)
#include <cuda_runtime.h>
#include <math.h>

// Problem shape: B=16, S=2048, D=768
#define MAXB 16
#define MAXS 2048
#define MAXD 768
#define NCHUNK 16   // o-dim chunks for fuse partials

// Scratch (device globals — no allocation allowed)
__device__ float g_part[NCHUNK * MAXD * 3];  // fuse partials [chunk][p]
__device__ float g_w2[MAXD * 3];             // fused conv*linear weights [i*3+k]
__device__ float g_c;                        // fused bias
__device__ float g_z0[MAXB * MAXS];          // per-row dot with w2[:,k]
__device__ float g_z1[MAXB * MAXS];
__device__ float g_z2[MAXB * MAXS];
__device__ float g_alpha[MAXB * MAXS];
__device__ int   g_Ft[MAXB * MAXS];          // fire time indices (compacted)
__device__ float g_Fa1[MAXB * MAXS];         // a1 at fire j
__device__ float g_Fa2[MAXB * MAXS];         // a2 at fire j
__device__ int   g_n[MAXB];

// ---------------------------------------------------------------------------
// Kernel 1a: partial fuse. grid = (9 p-blocks, NCHUNK o-chunks), 256 thr.
// g_part[ch][p] = sum_{o in chunk} lin_w[o] * conv_w[o*3D + p]
// ---------------------------------------------------------------------------
__global__ void k_fuse_part(const float* __restrict__ conv_w,
                            const float* __restrict__ lin_w, int D) {
    const int p = blockIdx.x * 256 + threadIdx.x;     // p = i*3+k
    const int P = D * 3;
    if (p >= P) return;
    const int ch = blockIdx.y;
    const int csz = D / NCHUNK;
    const int o0 = ch * csz;
    float acc = 0.f;
    #pragma unroll 4
    for (int o = o0; o < o0 + csz; o++)
        acc += lin_w[o] * conv_w[(size_t)o * P + p];
    g_part[ch * P + p] = acc;
}

// ---------------------------------------------------------------------------
// Kernel 1b: combine partials (fixed order) + c scalar. 10 blocks of 256.
// ---------------------------------------------------------------------------
__global__ void k_fuse_comb(const float* __restrict__ conv_b,
                            const float* __restrict__ lin_w,
                            const float* __restrict__ lin_b, int D) {
    const int P = D * 3;
    if ((int)blockIdx.x == (int)gridDim.x - 1) {
        __shared__ float red[256];
        float s = 0.f;
        for (int o = threadIdx.x; o < D; o += 256) s += lin_w[o] * conv_b[o];
        red[threadIdx.x] = s;
        __syncthreads();
        for (int st = 128; st > 0; st >>= 1) {
            if ((int)threadIdx.x < st) red[threadIdx.x] += red[threadIdx.x + st];
            __syncthreads();
        }
        if (threadIdx.x == 0) g_c = red[0] + lin_b[0];
    } else {
        int p = blockIdx.x * 256 + threadIdx.x;
        if (p < P) {
            float acc = 0.f;
            #pragma unroll
            for (int ch = 0; ch < NCHUNK; ch++) acc += g_part[ch * P + p];
            g_w2[p] = acc;
        }
    }
}

// ---------------------------------------------------------------------------
// Kernel 2: z_k[r] = dot(x[r], w2[:,k]) for k=0..2. Warp per row, 8 warps/blk.
// x read exactly once. D==768 path: all 6 LDG.128 front-batched (MLP=6).
// ---------------------------------------------------------------------------
__global__ void k_z(const float* __restrict__ x, int S, int D) {
    __shared__ __align__(16) float sw2[3 * MAXD];
    for (int idx = threadIdx.x; idx < D * 3; idx += blockDim.x) {
        int i = idx / 3, k = idx - i * 3;
        sw2[k * D + i] = g_w2[idx];
    }
    __syncthreads();

    const int b = blockIdx.y;
    const int warp = threadIdx.x >> 5, lane = threadIdx.x & 31;
    const int r = blockIdx.x * 8 + warp;
    if (r >= S) return;

    const float4* xr  = (const float4*)(x + ((size_t)b * S + r) * D);
    const float4* w0  = (const float4*)(sw2);
    const float4* w1  = (const float4*)(sw2 + D);
    const float4* w2p = (const float4*)(sw2 + 2 * D);
    float a0 = 0.f, a1 = 0.f, a2 = 0.f;

    if (D == MAXD) {
        // 768/4 = 192 float4; 6 per lane. Front-batch all global loads.
        float4 xv[6];
        #pragma unroll
        for (int u = 0; u < 6; u++) xv[u] = xr[lane + 32 * u];
        #pragma unroll
        for (int u = 0; u < 6; u++) {
            const int m = lane + 32 * u;
            float4 uu = w0[m];
            a0 += uu.x * xv[u].x + uu.y * xv[u].y + uu.z * xv[u].z + uu.w * xv[u].w;
            float4 vv = w1[m];
            a1 += vv.x * xv[u].x + vv.y * xv[u].y + vv.z * xv[u].z + vv.w * xv[u].w;
            float4 ww = w2p[m];
            a2 += ww.x * xv[u].x + ww.y * xv[u].y + ww.z * xv[u].z + ww.w * xv[u].w;
        }
    } else {
        const int M = D >> 2;
        for (int m = lane; m < M; m += 32) {
            float4 xv = xr[m];
            float4 uu = w0[m];
            a0 += uu.x * xv.x + uu.y * xv.y + uu.z * xv.z + uu.w * xv.w;
            float4 vv = w1[m];
            a1 += vv.x * xv.x + vv.y * xv.y + vv.z * xv.z + vv.w * xv.w;
            float4 ww = w2p[m];
            a2 += ww.x * xv.x + ww.y * xv.y + ww.z * xv.z + ww.w * xv.w;
        }
    }
    #pragma unroll
    for (int o = 16; o > 0; o >>= 1) {
        a0 += __shfl_xor_sync(0xffffffffu, a0, o);
        a1 += __shfl_xor_sync(0xffffffffu, a1, o);
        a2 += __shfl_xor_sync(0xffffffffu, a2, o);
    }
    if (lane == 0) {
        size_t idx = (size_t)b * S + r;
        g_z0[idx] = a0; g_z1[idx] = a1; g_z2[idx] = a2;
    }
}

// ---------------------------------------------------------------------------
// Kernel 3: alpha compute (folded from k_comb) + sequential CIF scan.
// One block per batch. Load phase: 256 threads compute
//   alpha[t] = sigmoid(c + z0[t-1] + z1[t] + z2[t+1]) for t < len, else 0,
// into smem AND g_alpha (emit reads it). Then thread 0 runs the exact
// reference-ordered fire chain up to len (aacc<1 invariant => no fires after).
// ---------------------------------------------------------------------------
__global__ void k_scan(const int* __restrict__ lens, int S) {
    __shared__ float sa[MAXS];
    __shared__ int   sFt[MAXS];
    __shared__ float sA1[MAXS];
    __shared__ float sA2[MAXS];
    __shared__ int   s_nf;
    const int b = blockIdx.x;
    const int base = b * S;
    const int len = lens[b];
    const float c = g_c;

    for (int t = threadIdx.x; t < S; t += blockDim.x) {
        float a = 0.f;
        if (t < len) {
            float l = c + g_z1[base + t];
            if (t > 0)     l += g_z0[base + t - 1];
            if (t < S - 1) l += g_z2[base + t + 1];
            a = 1.f / (1.f + expf(-l));
        }
        sa[t] = a;
        g_alpha[base + t] = a;
    }
    __syncthreads();

    if (threadIdx.x == 0) {
        float aacc = 0.f;
        int nf = 0;
        #pragma unroll 4
        for (int t = 0; t < len; t++) {
            float a  = sa[t];
            float s1 = aacc + a;           // aacc_u        (FADD, on chain)
            float a1 = 1.0f - aacc;        // fire weight   (parallel)
            float a2 = a - a1;             // leftover
            bool fire = (s1 >= 1.0f);      // FSETP -> data
            sFt[nf] = t; sA1[nf] = a1; sA2[nf] = a2;   // off-chain record
            nf += fire ? 1 : 0;
            aacc = fire ? a2 : s1;         // FSEL
        }
        s_nf = nf;
        g_n[b] = nf;
    }
    __syncthreads();
    const int nf = s_nf;
    for (int i = threadIdx.x; i < nf; i += blockDim.x) {
        g_Ft[base + i]  = sFt[i];
        g_Fa1[base + i] = sA1[i];
        g_Fa2[base + i] = sA2[i];
    }
}

// ---------------------------------------------------------------------------
// Kernel 4: emit. Block (jb, b) handles 4 output rows. Row j < n:
// sum over t in [F[j-1], F[j]] with weight alpha[t] (interior),
// a2[j-1] at t0 (j>0), a1[j] at t1. Rows >= n: zeros.
// ---------------------------------------------------------------------------
__global__ void k_emit(const float* __restrict__ x, float* __restrict__ out,
                       int B, int S, int D, long long out_size) {
    const int b = blockIdx.y;
    const int tid = threadIdx.x;
    const int n = g_n[b];
    const int base = b * S;
    const int j0 = blockIdx.x * 4;

    #pragma unroll
    for (int jj = 0; jj < 4; jj++) {
        const int j = j0 + jj;
        if (j >= S) break;
        float4* orow = (float4*)(out + ((size_t)b * S + j) * D);
        if (j >= n) {
            orow[tid] = make_float4(0.f, 0.f, 0.f, 0.f);
        } else {
            const int t1 = g_Ft[base + j];
            const int t0 = (j == 0) ? 0 : g_Ft[base + j - 1];
            const float wa1 = g_Fa1[base + j];
            const float wa2 = (j == 0) ? 0.f : g_Fa2[base + j - 1];
            float4 acc = make_float4(0.f, 0.f, 0.f, 0.f);
            #pragma unroll 4
            for (int t = t0; t <= t1; t++) {
                float wgt = (t == t1) ? wa1
                          : ((j > 0 && t == t0) ? wa2 : g_alpha[base + t]);
                const float4 h = ((const float4*)(x + ((size_t)b * S + t) * D))[tid];
                acc.x += wgt * h.x; acc.y += wgt * h.y;
                acc.z += wgt * h.z; acc.w += wgt * h.w;
            }
            orow[tid] = acc;
        }
    }
    // len_tensor appended after output_c, if space exists
    if (blockIdx.x == 0 && tid == 0 && out_size >= (long long)B * S * D + B)
        out[(size_t)B * S * D + b] = (float)n;
}

// ---------------------------------------------------------------------------
extern "C" void kernel_launch(void* const* d_in, const int* in_sizes, int n_in,
                              void* d_out, int out_size) {
    const float* x      = (const float*)d_in[0];  // (B,S,D)
    const int*   lens   = (const int*)  d_in[1];  // (B,)
    const float* conv_w = (const float*)d_in[2];  // (D,D,3)
    const float* conv_b = (const float*)d_in[3];  // (D,)
    const float* lin_w  = (const float*)d_in[4];  // (1,D)
    const float* lin_b  = (const float*)d_in[5];  // (1,)

    const int B = in_sizes[1];
    const int D = in_sizes[4];
    const int S = in_sizes[0] / (B * D);
    float* out = (float*)d_out;

    // 1) fuse weights (parallel partials + fixed-order combine)
    {
        dim3 g1((D * 3 + 255) / 256, NCHUNK);
        k_fuse_part<<<g1, 256>>>(conv_w, lin_w, D);
        k_fuse_comb<<<(D * 3 + 255) / 256 + 1, 256>>>(conv_b, lin_w, lin_b, D);
    }
    // 2) per-row conv-tap dots (x read once)
    {
        dim3 grid((S + 7) / 8, B);
        k_z<<<grid, 256>>>(x, S, D);
    }
    // 3) alpha + sequential scan per batch (comb folded in)
    k_scan<<<B, 256>>>(lens, S);
    // 4) emit output rows + lens
    {
        dim3 grid((S + 3) / 4, B);
        k_emit<<<grid, D / 4>>>(x, out, B, S, D, (long long)out_size);
    }
}

// round 7
// speedup vs baseline: 1.5668x; 1.5668x over previous
#include <cuda_runtime.h>
#include <math.h>

// Problem shape: B=16, S=2048, D=768
#define MAXB 16
#define MAXS 2048
#define MAXD 768
#define NCHUNK 16   // o-dim chunks for fuse partials

// Scratch (device globals — no allocation allowed)
__device__ float g_part[NCHUNK * MAXD * 3];  // fuse partials [chunk][p]
__device__ float g_w2[MAXD * 3];             // fused conv*linear weights [i*3+k]
__device__ float g_c;                        // fused bias
__device__ float g_z0[MAXB * MAXS];          // per-row dot with w2[:,k]
__device__ float g_z1[MAXB * MAXS];
__device__ float g_z2[MAXB * MAXS];
__device__ float g_alpha[MAXB * MAXS];
__device__ int   g_Ft[MAXB * MAXS];          // fire time indices (compacted)
__device__ float g_Fa1[MAXB * MAXS];         // a1 at fire j
__device__ float g_Fa2[MAXB * MAXS];         // a2 at fire j
__device__ int   g_n[MAXB];

// ---------------------------------------------------------------------------
// Kernel 1a: partial fuse. grid = (9 p-blocks, NCHUNK o-chunks), 256 thr.
// ---------------------------------------------------------------------------
__global__ void k_fuse_part(const float* __restrict__ conv_w,
                            const float* __restrict__ lin_w, int D) {
    const int p = blockIdx.x * 256 + threadIdx.x;     // p = i*3+k
    const int P = D * 3;
    if (p >= P) return;
    const int ch = blockIdx.y;
    const int csz = D / NCHUNK;
    const int o0 = ch * csz;
    float acc = 0.f;
    #pragma unroll 4
    for (int o = o0; o < o0 + csz; o++)
        acc += lin_w[o] * conv_w[(size_t)o * P + p];
    g_part[ch * P + p] = acc;
}

// ---------------------------------------------------------------------------
// Kernel 1b: combine partials (fixed order) + c scalar.
// ---------------------------------------------------------------------------
__global__ void k_fuse_comb(const float* __restrict__ conv_b,
                            const float* __restrict__ lin_w,
                            const float* __restrict__ lin_b, int D) {
    const int P = D * 3;
    if ((int)blockIdx.x == (int)gridDim.x - 1) {
        __shared__ float red[256];
        float s = 0.f;
        for (int o = threadIdx.x; o < D; o += 256) s += lin_w[o] * conv_b[o];
        red[threadIdx.x] = s;
        __syncthreads();
        for (int st = 128; st > 0; st >>= 1) {
            if ((int)threadIdx.x < st) red[threadIdx.x] += red[threadIdx.x + st];
            __syncthreads();
        }
        if (threadIdx.x == 0) g_c = red[0] + lin_b[0];
    } else {
        int p = blockIdx.x * 256 + threadIdx.x;
        if (p < P) {
            float acc = 0.f;
            #pragma unroll
            for (int ch = 0; ch < NCHUNK; ch++) acc += g_part[ch * P + p];
            g_w2[p] = acc;
        }
    }
}

// ---------------------------------------------------------------------------
// Kernel 2: z_k[r] = dot(x[r], w2[:,k]). Warp per row, 8 warps/blk.
// x read exactly once; D==768 path front-batches all 6 LDG.128 (MLP=6).
// ---------------------------------------------------------------------------
__global__ void k_z(const float* __restrict__ x, int S, int D) {
    __shared__ __align__(16) float sw2[3 * MAXD];
    for (int idx = threadIdx.x; idx < D * 3; idx += blockDim.x) {
        int i = idx / 3, k = idx - i * 3;
        sw2[k * D + i] = g_w2[idx];
    }
    __syncthreads();

    const int b = blockIdx.y;
    const int warp = threadIdx.x >> 5, lane = threadIdx.x & 31;
    const int r = blockIdx.x * 8 + warp;
    if (r >= S) return;

    const float4* xr  = (const float4*)(x + ((size_t)b * S + r) * D);
    const float4* w0  = (const float4*)(sw2);
    const float4* w1  = (const float4*)(sw2 + D);
    const float4* w2p = (const float4*)(sw2 + 2 * D);
    float a0 = 0.f, a1 = 0.f, a2 = 0.f;

    if (D == MAXD) {
        float4 xv[6];
        #pragma unroll
        for (int u = 0; u < 6; u++) xv[u] = xr[lane + 32 * u];
        #pragma unroll
        for (int u = 0; u < 6; u++) {
            const int m = lane + 32 * u;
            float4 uu = w0[m];
            a0 += uu.x * xv[u].x + uu.y * xv[u].y + uu.z * xv[u].z + uu.w * xv[u].w;
            float4 vv = w1[m];
            a1 += vv.x * xv[u].x + vv.y * xv[u].y + vv.z * xv[u].z + vv.w * xv[u].w;
            float4 ww = w2p[m];
            a2 += ww.x * xv[u].x + ww.y * xv[u].y + ww.z * xv[u].z + ww.w * xv[u].w;
        }
    } else {
        const int M = D >> 2;
        for (int m = lane; m < M; m += 32) {
            float4 xv = xr[m];
            float4 uu = w0[m];
            a0 += uu.x * xv.x + uu.y * xv.y + uu.z * xv.z + uu.w * xv.w;
            float4 vv = w1[m];
            a1 += vv.x * xv.x + vv.y * xv.y + vv.z * xv.z + vv.w * xv.w;
            float4 ww = w2p[m];
            a2 += ww.x * xv.x + ww.y * xv.y + ww.z * xv.z + ww.w * xv.w;
        }
    }
    #pragma unroll
    for (int o = 16; o > 0; o >>= 1) {
        a0 += __shfl_xor_sync(0xffffffffu, a0, o);
        a1 += __shfl_xor_sync(0xffffffffu, a1, o);
        a2 += __shfl_xor_sync(0xffffffffu, a2, o);
    }
    if (lane == 0) {
        size_t idx = (size_t)b * S + r;
        g_z0[idx] = a0; g_z1[idx] = a1; g_z2[idx] = a2;
    }
}

// ---------------------------------------------------------------------------
// Kernel 3: alpha compute + sequential CIF scan, one block/batch.
// Load phase: 256 threads compute alpha -> smem + g_alpha (0 beyond len).
// Serial phase: thread 0, chunks of 16 — four front-batched LDS.128 into a
// fully-unrolled register array, then a pure register fire chain
// (FADD -> FSETP -> FSEL, ~12 cyc/iter). Zero-alpha steps beyond len are
// exact no-ops (aacc < 1 invariant), so fixed trip count S, no branches.
// Op order on the chain is bit-identical to the reference.
// ---------------------------------------------------------------------------
__global__ void k_scan(const int* __restrict__ lens, int S) {
    __shared__ __align__(16) float sa[MAXS];
    __shared__ int   sFt[MAXS];
    __shared__ float sA1[MAXS];
    __shared__ float sA2[MAXS];
    __shared__ int   s_nf;
    const int b = blockIdx.x;
    const int base = b * S;
    const int len = lens[b];
    const float c = g_c;

    for (int t = threadIdx.x; t < S; t += blockDim.x) {
        float a = 0.f;
        if (t < len) {
            float l = c + g_z1[base + t];
            if (t > 0)     l += g_z0[base + t - 1];
            if (t < S - 1) l += g_z2[base + t + 1];
            a = 1.f / (1.f + expf(-l));
        }
        sa[t] = a;
        g_alpha[base + t] = a;
    }
    __syncthreads();

    if (threadIdx.x == 0) {
        float aacc = 0.f;
        int nf = 0;
        for (int tb = 0; tb < S; tb += 16) {
            // front-batched shared loads (off the fire chain)
            float4 q0 = *(const float4*)(sa + tb);
            float4 q1 = *(const float4*)(sa + tb + 4);
            float4 q2 = *(const float4*)(sa + tb + 8);
            float4 q3 = *(const float4*)(sa + tb + 12);
            float av[16] = { q0.x, q0.y, q0.z, q0.w,
                             q1.x, q1.y, q1.z, q1.w,
                             q2.x, q2.y, q2.z, q2.w,
                             q3.x, q3.y, q3.z, q3.w };
            #pragma unroll
            for (int u = 0; u < 16; u++) {
                float a  = av[u];
                float s1 = aacc + a;           // aacc_u     (on chain)
                float a1 = 1.0f - aacc;        // fire weight
                float a2 = a - a1;             // leftover
                bool fire = (s1 >= 1.0f);
                sFt[nf] = tb + u; sA1[nf] = a1; sA2[nf] = a2;  // off-chain
                nf += fire ? 1 : 0;
                aacc = fire ? a2 : s1;         // FSEL
            }
        }
        s_nf = nf;
        g_n[b] = nf;
    }
    __syncthreads();
    const int nf = s_nf;
    for (int i = threadIdx.x; i < nf; i += blockDim.x) {
        g_Ft[base + i]  = sFt[i];
        g_Fa1[base + i] = sA1[i];
        g_Fa2[base + i] = sA2[i];
    }
}

// ---------------------------------------------------------------------------
// Kernel 4: emit. Block (jb, b) handles 4 output rows. Row j < n:
// sum over t in [F[j-1], F[j]] with weight alpha[t] (interior),
// a2[j-1] at t0 (j>0), a1[j] at t1. Rows >= n: zeros.
// ---------------------------------------------------------------------------
__global__ void k_emit(const float* __restrict__ x, float* __restrict__ out,
                       int B, int S, int D, long long out_size) {
    const int b = blockIdx.y;
    const int tid = threadIdx.x;
    const int n = g_n[b];
    const int base = b * S;
    const int j0 = blockIdx.x * 4;

    #pragma unroll
    for (int jj = 0; jj < 4; jj++) {
        const int j = j0 + jj;
        if (j >= S) break;
        float4* orow = (float4*)(out + ((size_t)b * S + j) * D);
        if (j >= n) {
            orow[tid] = make_float4(0.f, 0.f, 0.f, 0.f);
        } else {
            const int t1 = g_Ft[base + j];
            const int t0 = (j == 0) ? 0 : g_Ft[base + j - 1];
            const float wa1 = g_Fa1[base + j];
            const float wa2 = (j == 0) ? 0.f : g_Fa2[base + j - 1];
            float4 acc = make_float4(0.f, 0.f, 0.f, 0.f);
            #pragma unroll 4
            for (int t = t0; t <= t1; t++) {
                float wgt = (t == t1) ? wa1
                          : ((j > 0 && t == t0) ? wa2 : g_alpha[base + t]);
                const float4 h = ((const float4*)(x + ((size_t)b * S + t) * D))[tid];
                acc.x += wgt * h.x; acc.y += wgt * h.y;
                acc.z += wgt * h.z; acc.w += wgt * h.w;
            }
            orow[tid] = acc;
        }
    }
    if (blockIdx.x == 0 && tid == 0 && out_size >= (long long)B * S * D + B)
        out[(size_t)B * S * D + b] = (float)n;
}

// ---------------------------------------------------------------------------
extern "C" void kernel_launch(void* const* d_in, const int* in_sizes, int n_in,
                              void* d_out, int out_size) {
    const float* x      = (const float*)d_in[0];  // (B,S,D)
    const int*   lens   = (const int*)  d_in[1];  // (B,)
    const float* conv_w = (const float*)d_in[2];  // (D,D,3)
    const float* conv_b = (const float*)d_in[3];  // (D,)
    const float* lin_w  = (const float*)d_in[4];  // (1,D)
    const float* lin_b  = (const float*)d_in[5];  // (1,)

    const int B = in_sizes[1];
    const int D = in_sizes[4];
    const int S = in_sizes[0] / (B * D);
    float* out = (float*)d_out;

    {
        dim3 g1((D * 3 + 255) / 256, NCHUNK);
        k_fuse_part<<<g1, 256>>>(conv_w, lin_w, D);
        k_fuse_comb<<<(D * 3 + 255) / 256 + 1, 256>>>(conv_b, lin_w, lin_b, D);
    }
    {
        dim3 grid((S + 7) / 8, B);
        k_z<<<grid, 256>>>(x, S, D);
    }
    k_scan<<<B, 256>>>(lens, S);
    {
        dim3 grid((S + 3) / 4, B);
        k_emit<<<grid, D / 4>>>(x, out, B, S, D, (long long)out_size);
    }
}